// round 2
// baseline (speedup 1.0000x reference)
#include <cuda_runtime.h>
#include <math.h>

// Model dims
#define NB      16      // batch rows per block
#define NTH     256     // threads per block
#define RPT     16      // rows per thread-group (NB, single group)
#define HD      256     // hidden
#define TV      64      // vocab
#define TSTEPS  119     // T-1

// ---------------- device-global scratch (allowed; no runtime alloc) ----------
// Transposed weights, packed as [k4][768] of float4 (4 consecutive k per unit j)
__device__ float4 g_whT[3][64 * 768];   // w_hh for layers 0,1,2
__device__ float4 g_wiT[2][64 * 768];   // w_ih for layers 1,2
__device__ float4 g_owT[64 * 64];       // out_w: [k4][64] float4
__device__ float  g_table[64 * 768];    // emb @ w_ih0^T + b_ih0  (layer-0 input table)

// ---------------- accurate activations (safe under fast-math) ---------------
__device__ __forceinline__ float sigf(float x) {
    return 1.0f / (1.0f + expf(-x));
}
__device__ __forceinline__ float tanh_acc(float x) {
    float ax = fabsf(x);
    float e  = expf(-2.0f * ax);
    float t  = (1.0f - e) / (1.0f + e);
    return (x >= 0.0f) ? t : -t;
}

// ---------------- prep: transposes + layer0 input table ---------------------
__global__ void prep_kernel(const float* __restrict__ w_hh0,
                            const float* __restrict__ w_hh1,
                            const float* __restrict__ w_hh2,
                            const float* __restrict__ w_ih1,
                            const float* __restrict__ w_ih2,
                            const float* __restrict__ out_w,
                            const float* __restrict__ emb,
                            const float* __restrict__ w_ih0,
                            const float* __restrict__ b_ih0)
{
    int idx    = blockIdx.x * blockDim.x + threadIdx.x;
    int stride = gridDim.x * blockDim.x;

    // 768x256 matrices -> [k4][row][kk]
    for (int e = idx; e < 768 * 256; e += stride) {
        int row = e >> 8;
        int k   = e & 255;
        int di  = (k >> 2) * 768 + row;
        int kk  = k & 3;
        ((float*)&g_whT[0][di])[kk] = w_hh0[e];
        ((float*)&g_whT[1][di])[kk] = w_hh1[e];
        ((float*)&g_whT[2][di])[kk] = w_hh2[e];
        ((float*)&g_wiT[0][di])[kk] = w_ih1[e];
        ((float*)&g_wiT[1][di])[kk] = w_ih2[e];
    }
    // out_w 64x256 -> [k4][v]
    for (int e = idx; e < 64 * 256; e += stride) {
        int v = e >> 8;
        int k = e & 255;
        ((float*)&g_owT[(k >> 2) * 64 + v])[k & 3] = out_w[e];
    }
    // table[v][j] = b_ih0[j] + sum_t emb[v][t] * w_ih0[j][t]
    for (int e = idx; e < 64 * 768; e += stride) {
        int v  = e / 768;
        int jj = e - v * 768;
        const float* er = emb   + v  * 64;
        const float* wr = w_ih0 + jj * 64;
        float acc = b_ih0[jj];
        #pragma unroll 8
        for (int t = 0; t < 64; ++t) acc = fmaf(er[t], wr[t], acc);
        g_table[e] = acc;
    }
}

// Triple-stream GEMM accumulate: a0 += w_r . x ; a1 += w_z . x ; a2 += w_n . x
// w4: [64*768] float4 (k-vectorized, j-coalesced). xb: SMEM rows (stride HD).
__device__ __forceinline__ void gemm3(const float4* __restrict__ w4,
                                      const float*  __restrict__ xb,
                                      int j,
                                      float* __restrict__ a0,
                                      float* __restrict__ a1,
                                      float* __restrict__ a2)
{
    #pragma unroll 2
    for (int k4 = 0; k4 < 64; ++k4) {
        float4 wr = w4[k4 * 768 + j];
        float4 wz = w4[k4 * 768 + j + 256];
        float4 wn = w4[k4 * 768 + j + 512];
        const float* xk = xb + k4 * 4;
        #pragma unroll
        for (int bb = 0; bb < RPT; ++bb) {
            float4 xv = *reinterpret_cast<const float4*>(xk + bb * HD);
            a0[bb] = fmaf(wr.w, xv.w, fmaf(wr.z, xv.z, fmaf(wr.y, xv.y, fmaf(wr.x, xv.x, a0[bb]))));
            a1[bb] = fmaf(wz.w, xv.w, fmaf(wz.z, xv.z, fmaf(wz.y, xv.y, fmaf(wz.x, xv.x, a1[bb]))));
            a2[bb] = fmaf(wn.w, xv.w, fmaf(wn.z, xv.z, fmaf(wn.y, xv.y, fmaf(wn.x, xv.x, a2[bb]))));
        }
    }
}

// ---------------- main persistent decoder ------------------------------------
__global__ void __launch_bounds__(NTH, 1)
decoder_kernel(const float* __restrict__ z,
               const float* __restrict__ z2h_w,
               const float* __restrict__ z2h_b,
               const float* __restrict__ b_hh0,
               const float* __restrict__ b_ih1, const float* __restrict__ b_hh1,
               const float* __restrict__ b_ih2, const float* __restrict__ b_hh2,
               const float* __restrict__ out_b,
               float* __restrict__ out)
{
    extern __shared__ float smem[];
    float* hbuf = smem;                         // [3][NB][HD]
    float* slog = smem + 3 * NB * HD;           // [NB][TV]
    int*   stok = (int*)(slog + NB * TV);       // [NB]

    const int tid = threadIdx.x;
    const int b0  = blockIdx.x * NB;
    const int j   = tid;                        // 0..255 (hidden unit)

    // ---- init h0 = tanh(z @ z2h_w^T + z2h_b), tokens = 1
    for (int idx = tid; idx < NB * 768; idx += NTH) {
        int b = idx / 768;
        int u = idx - b * 768;                  // u = l*256 + jj
        const float* wr = z2h_w + u * 128;
        const float* zr = z + (size_t)(b0 + b) * 128;
        float acc = z2h_b[u];
        #pragma unroll 8
        for (int k = 0; k < 128; ++k) acc = fmaf(wr[k], zr[k], acc);
        int l  = u >> 8;
        int jj = u & 255;
        hbuf[(l * NB + b) * HD + jj] = tanh_acc(acc);
    }
    if (tid < NB) stok[tid] = 1;
    __syncthreads();

    // ---- hoisted per-thread constants
    const float c0r = b_hh0[j], c0z = b_hh0[j + 256], c0n = b_hh0[j + 512];
    const float c1r = b_ih1[j] + b_hh1[j];
    const float c1z = b_ih1[j + 256] + b_hh1[j + 256];
    const float c1i = b_ih1[j + 512];
    const float c1h = b_hh1[j + 512];
    const float c2r = b_ih2[j] + b_hh2[j];
    const float c2z = b_ih2[j + 256] + b_hh2[j + 256];
    const float c2i = b_ih2[j + 512];
    const float c2h = b_hh2[j + 512];
    const int   vv  = tid & 63;
    const int   rg  = tid >> 6;                 // 0..3 (4 rows each)
    const float ob  = out_b[vv];

    const float* hb0 = hbuf + (0 * NB) * HD;
    const float* hb1 = hbuf + (1 * NB) * HD;
    const float* hb2 = hbuf + (2 * NB) * HD;

    float ar[RPT], az[RPT], ai[RPT], ah[RPT], hnew[RPT];

    for (int t = 0; t < TSTEPS; ++t) {
        // ================= layer 0 (input side = token table) ================
        #pragma unroll
        for (int bb = 0; bb < RPT; ++bb) {
            const float* trow = g_table + stok[bb] * 768;
            ar[bb] = trow[j]       + c0r;
            az[bb] = trow[j + 256] + c0z;
            ai[bb] = trow[j + 512];
            ah[bb] = c0n;
        }
        gemm3(g_whT[0], hb0, j, ar, az, ah);
        #pragma unroll
        for (int bb = 0; bb < RPT; ++bb) {
            float r  = sigf(ar[bb]);
            float u  = sigf(az[bb]);
            float n  = tanh_acc(fmaf(r, ah[bb], ai[bb]));
            float ho = hb0[bb * HD + j];
            hnew[bb] = (1.0f - u) * n + u * ho;
        }
        __syncthreads();
        #pragma unroll
        for (int bb = 0; bb < RPT; ++bb) hbuf[(0 * NB + bb) * HD + j] = hnew[bb];
        __syncthreads();

        // ================= layer 1 ==========================================
        #pragma unroll
        for (int bb = 0; bb < RPT; ++bb) { ar[bb] = c1r; az[bb] = c1z; ai[bb] = c1i; ah[bb] = c1h; }
        gemm3(g_wiT[0], hb0, j, ar, az, ai);
        gemm3(g_whT[1], hb1, j, ar, az, ah);
        #pragma unroll
        for (int bb = 0; bb < RPT; ++bb) {
            float r  = sigf(ar[bb]);
            float u  = sigf(az[bb]);
            float n  = tanh_acc(fmaf(r, ah[bb], ai[bb]));
            float ho = hb1[bb * HD + j];
            hnew[bb] = (1.0f - u) * n + u * ho;
        }
        __syncthreads();
        #pragma unroll
        for (int bb = 0; bb < RPT; ++bb) hbuf[(1 * NB + bb) * HD + j] = hnew[bb];
        __syncthreads();

        // ================= layer 2 ==========================================
        #pragma unroll
        for (int bb = 0; bb < RPT; ++bb) { ar[bb] = c2r; az[bb] = c2z; ai[bb] = c2i; ah[bb] = c2h; }
        gemm3(g_wiT[1], hb1, j, ar, az, ai);
        gemm3(g_whT[2], hb2, j, ar, az, ah);
        #pragma unroll
        for (int bb = 0; bb < RPT; ++bb) {
            float r  = sigf(ar[bb]);
            float u  = sigf(az[bb]);
            float n  = tanh_acc(fmaf(r, ah[bb], ai[bb]));
            float ho = hb2[bb * HD + j];
            hnew[bb] = (1.0f - u) * n + u * ho;
        }
        __syncthreads();
        #pragma unroll
        for (int bb = 0; bb < RPT; ++bb) hbuf[(2 * NB + bb) * HD + j] = hnew[bb];
        __syncthreads();

        // ================= logits + argmax ==================================
        // 256 threads: vv = tid&63 (vocab), rg = tid>>6 selects 4 rows
        float acc4[4] = {0.f, 0.f, 0.f, 0.f};
        const float* h2b = hbuf + (2 * NB + rg * 4) * HD;
        #pragma unroll 2
        for (int k4 = 0; k4 < 64; ++k4) {
            float4 wv = g_owT[k4 * 64 + vv];
            const float* hk = h2b + k4 * 4;
            #pragma unroll
            for (int rr = 0; rr < 4; ++rr) {
                float4 hv = *reinterpret_cast<const float4*>(hk + rr * HD);
                acc4[rr] = fmaf(wv.w, hv.w, fmaf(wv.z, hv.z, fmaf(wv.y, hv.y, fmaf(wv.x, hv.x, acc4[rr]))));
            }
        }
        #pragma unroll
        for (int rr = 0; rr < 4; ++rr) {
            float lv  = acc4[rr] + ob;
            int   row = rg * 4 + rr;
            slog[row * TV + vv] = lv;
            out[((size_t)(b0 + row) * TSTEPS + t) * TV + vv] = lv;
        }
        __syncthreads();
        if (tid < NB) {
            const float* lr = slog + tid * TV;
            float best = lr[0];
            int   bi   = 0;
            #pragma unroll 8
            for (int v2 = 1; v2 < TV; ++v2) {
                float lvv = lr[v2];
                if (lvv > best) { best = lvv; bi = v2; }   // first-max semantics
            }
            stok[tid] = bi;
        }
        __syncthreads();
    }
}

// ---------------- launch ------------------------------------------------------
extern "C" void kernel_launch(void* const* d_in, const int* in_sizes, int n_in,
                              void* d_out, int out_size)
{
    const float* z     = (const float*)d_in[0];
    const float* emb   = (const float*)d_in[1];
    const float* z2h_w = (const float*)d_in[2];
    const float* z2h_b = (const float*)d_in[3];
    const float* out_w = (const float*)d_in[4];
    const float* out_b = (const float*)d_in[5];
    const float* w_ih0 = (const float*)d_in[6];
    const float* w_hh0 = (const float*)d_in[7];
    const float* b_ih0 = (const float*)d_in[8];
    const float* b_hh0 = (const float*)d_in[9];
    const float* w_ih1 = (const float*)d_in[10];
    const float* w_hh1 = (const float*)d_in[11];
    const float* b_ih1 = (const float*)d_in[12];
    const float* b_hh1 = (const float*)d_in[13];
    const float* w_ih2 = (const float*)d_in[14];
    const float* w_hh2 = (const float*)d_in[15];
    const float* b_ih2 = (const float*)d_in[16];
    const float* b_hh2 = (const float*)d_in[17];

    prep_kernel<<<768, 256>>>(w_hh0, w_hh1, w_hh2, w_ih1, w_ih2,
                              out_w, emb, w_ih0, b_ih0);

    const int smem = (3 * NB * HD + NB * TV) * (int)sizeof(float) + NB * (int)sizeof(int);
    cudaFuncSetAttribute(decoder_kernel, cudaFuncAttributeMaxDynamicSharedMemorySize, smem);

    decoder_kernel<<<4096 / NB, NTH, smem>>>(z, z2h_w, z2h_b,
                                             b_hh0, b_ih1, b_hh1, b_ih2, b_hh2,
                                             out_b, (float*)d_out);
}

// round 3
// speedup vs baseline: 1.1240x; 1.1240x over previous
#include <cuda_runtime.h>
#include <math.h>

// Model dims
#define NB      16      // batch rows per block
#define NTH     512     // threads per block (2 row-groups x 256 hidden units)
#define RPT     8       // rows per thread (NB / 2 groups)
#define HD      256     // hidden
#define TV      64      // vocab
#define TSTEPS  119     // T-1

// ---------------- device-global scratch (allowed; no runtime alloc) ----------
// Transposed weights, packed as [k4][768] of float4 (4 consecutive k per unit j)
__device__ float4 g_whT[3][64 * 768];   // w_hh for layers 0,1,2
__device__ float4 g_wiT[2][64 * 768];   // w_ih for layers 1,2
__device__ float4 g_owT[64 * 64];       // out_w: [k4][64] float4
__device__ float  g_table[64 * 768];    // emb @ w_ih0^T + b_ih0  (layer-0 input table)

// ---------------- accurate activations (safe under fast-math) ---------------
__device__ __forceinline__ float sigf(float x) {
    return 1.0f / (1.0f + expf(-x));
}
__device__ __forceinline__ float tanh_acc(float x) {
    float ax = fabsf(x);
    float e  = expf(-2.0f * ax);
    float t  = (1.0f - e) / (1.0f + e);
    return (x >= 0.0f) ? t : -t;
}

// ---------------- prep: transposes + layer0 input table ---------------------
__global__ void prep_kernel(const float* __restrict__ w_hh0,
                            const float* __restrict__ w_hh1,
                            const float* __restrict__ w_hh2,
                            const float* __restrict__ w_ih1,
                            const float* __restrict__ w_ih2,
                            const float* __restrict__ out_w,
                            const float* __restrict__ emb,
                            const float* __restrict__ w_ih0,
                            const float* __restrict__ b_ih0)
{
    int idx    = blockIdx.x * blockDim.x + threadIdx.x;
    int stride = gridDim.x * blockDim.x;

    // 768x256 matrices -> [k4][row][kk]
    for (int e = idx; e < 768 * 256; e += stride) {
        int row = e >> 8;
        int k   = e & 255;
        int di  = (k >> 2) * 768 + row;
        int kk  = k & 3;
        ((float*)&g_whT[0][di])[kk] = w_hh0[e];
        ((float*)&g_whT[1][di])[kk] = w_hh1[e];
        ((float*)&g_whT[2][di])[kk] = w_hh2[e];
        ((float*)&g_wiT[0][di])[kk] = w_ih1[e];
        ((float*)&g_wiT[1][di])[kk] = w_ih2[e];
    }
    // out_w 64x256 -> [k4][v]
    for (int e = idx; e < 64 * 256; e += stride) {
        int v = e >> 8;
        int k = e & 255;
        ((float*)&g_owT[(k >> 2) * 64 + v])[k & 3] = out_w[e];
    }
    // table[v][j] = b_ih0[j] + sum_t emb[v][t] * w_ih0[j][t]
    for (int e = idx; e < 64 * 768; e += stride) {
        int v  = e / 768;
        int jj = e - v * 768;
        const float* er = emb   + v  * 64;
        const float* wr = w_ih0 + jj * 64;
        float acc = b_ih0[jj];
        #pragma unroll 8
        for (int t = 0; t < 64; ++t) acc = fmaf(er[t], wr[t], acc);
        g_table[e] = acc;
    }
}

// Triple-stream GEMM accumulate: a0 += w_r . x ; a1 += w_z . x ; a2 += w_n . x
// w4: [64*768] float4 (k-vectorized, j-coalesced). xb: SMEM rows (stride HD).
__device__ __forceinline__ void gemm3(const float4* __restrict__ w4,
                                      const float*  __restrict__ xb,
                                      int j,
                                      float* __restrict__ a0,
                                      float* __restrict__ a1,
                                      float* __restrict__ a2)
{
    #pragma unroll 4
    for (int k4 = 0; k4 < 64; ++k4) {
        float4 wr = w4[k4 * 768 + j];
        float4 wz = w4[k4 * 768 + j + 256];
        float4 wn = w4[k4 * 768 + j + 512];
        const float* xk = xb + k4 * 4;
        #pragma unroll
        for (int bb = 0; bb < RPT; ++bb) {
            float4 xv = *reinterpret_cast<const float4*>(xk + bb * HD);
            a0[bb] = fmaf(wr.w, xv.w, fmaf(wr.z, xv.z, fmaf(wr.y, xv.y, fmaf(wr.x, xv.x, a0[bb]))));
            a1[bb] = fmaf(wz.w, xv.w, fmaf(wz.z, xv.z, fmaf(wz.y, xv.y, fmaf(wz.x, xv.x, a1[bb]))));
            a2[bb] = fmaf(wn.w, xv.w, fmaf(wn.z, xv.z, fmaf(wn.y, xv.y, fmaf(wn.x, xv.x, a2[bb]))));
        }
    }
}

// ---------------- main persistent decoder ------------------------------------
__global__ void __launch_bounds__(NTH, 1)
decoder_kernel(const float* __restrict__ z,
               const float* __restrict__ z2h_w,
               const float* __restrict__ z2h_b,
               const float* __restrict__ b_hh0,
               const float* __restrict__ b_ih1, const float* __restrict__ b_hh1,
               const float* __restrict__ b_ih2, const float* __restrict__ b_hh2,
               const float* __restrict__ out_b,
               float* __restrict__ out)
{
    extern __shared__ float smem[];
    float* hbuf = smem;                         // [3][NB][HD]
    float* slog = smem + 3 * NB * HD;           // [NB][TV]
    int*   stok = (int*)(slog + NB * TV);       // [NB]

    const int tid = threadIdx.x;
    const int b0  = blockIdx.x * NB;
    const int j   = tid & 255;                  // hidden unit
    const int g   = tid >> 8;                   // row group 0/1 (8 rows each)

    // ---- init h0 = tanh(z @ z2h_w^T + z2h_b), tokens = 1
    for (int idx = tid; idx < NB * 768; idx += NTH) {
        int b = idx / 768;
        int u = idx - b * 768;                  // u = l*256 + jj
        const float* wr = z2h_w + u * 128;
        const float* zr = z + (size_t)(b0 + b) * 128;
        float acc = z2h_b[u];
        #pragma unroll 8
        for (int k = 0; k < 128; ++k) acc = fmaf(wr[k], zr[k], acc);
        int l  = u >> 8;
        int jj = u & 255;
        hbuf[(l * NB + b) * HD + jj] = tanh_acc(acc);
    }
    if (tid < NB) stok[tid] = 1;
    __syncthreads();

    // ---- hoisted per-thread constants
    const float c0r = b_hh0[j], c0z = b_hh0[j + 256], c0n = b_hh0[j + 512];
    const float c1r = b_ih1[j] + b_hh1[j];
    const float c1z = b_ih1[j + 256] + b_hh1[j + 256];
    const float c1i = b_ih1[j + 512];
    const float c1h = b_hh1[j + 512];
    const float c2r = b_ih2[j] + b_hh2[j];
    const float c2z = b_ih2[j + 256] + b_hh2[j + 256];
    const float c2i = b_ih2[j + 512];
    const float c2h = b_hh2[j + 512];
    const int   vv  = tid & 63;
    const int   rg  = tid >> 6;                 // 0..7 (2 rows each)
    const float ob  = out_b[vv];

    const float* hb0 = hbuf + (0 * NB + g * RPT) * HD;
    const float* hb1 = hbuf + (1 * NB + g * RPT) * HD;
    const float* hb2 = hbuf + (2 * NB + g * RPT) * HD;

    float ar[RPT], az[RPT], ai[RPT], ah[RPT], hnew[RPT];

    for (int t = 0; t < TSTEPS; ++t) {
        // ================= layer 0 (input side = token table) ================
        #pragma unroll
        for (int bb = 0; bb < RPT; ++bb) {
            const float* trow = g_table + stok[g * RPT + bb] * 768;
            ar[bb] = trow[j]       + c0r;
            az[bb] = trow[j + 256] + c0z;
            ai[bb] = trow[j + 512];
            ah[bb] = c0n;
        }
        gemm3(g_whT[0], hb0, j, ar, az, ah);
        #pragma unroll
        for (int bb = 0; bb < RPT; ++bb) {
            float r  = sigf(ar[bb]);
            float u  = sigf(az[bb]);
            float n  = tanh_acc(fmaf(r, ah[bb], ai[bb]));
            float ho = hb0[bb * HD + j];
            hnew[bb] = (1.0f - u) * n + u * ho;
        }
        __syncthreads();
        #pragma unroll
        for (int bb = 0; bb < RPT; ++bb) hbuf[(0 * NB + g * RPT + bb) * HD + j] = hnew[bb];
        __syncthreads();

        // ================= layer 1 ==========================================
        #pragma unroll
        for (int bb = 0; bb < RPT; ++bb) { ar[bb] = c1r; az[bb] = c1z; ai[bb] = c1i; ah[bb] = c1h; }
        gemm3(g_wiT[0], hb0, j, ar, az, ai);
        gemm3(g_whT[1], hb1, j, ar, az, ah);
        #pragma unroll
        for (int bb = 0; bb < RPT; ++bb) {
            float r  = sigf(ar[bb]);
            float u  = sigf(az[bb]);
            float n  = tanh_acc(fmaf(r, ah[bb], ai[bb]));
            float ho = hb1[bb * HD + j];
            hnew[bb] = (1.0f - u) * n + u * ho;
        }
        __syncthreads();
        #pragma unroll
        for (int bb = 0; bb < RPT; ++bb) hbuf[(1 * NB + g * RPT + bb) * HD + j] = hnew[bb];
        __syncthreads();

        // ================= layer 2 ==========================================
        #pragma unroll
        for (int bb = 0; bb < RPT; ++bb) { ar[bb] = c2r; az[bb] = c2z; ai[bb] = c2i; ah[bb] = c2h; }
        gemm3(g_wiT[1], hb1, j, ar, az, ai);
        gemm3(g_whT[2], hb2, j, ar, az, ah);
        #pragma unroll
        for (int bb = 0; bb < RPT; ++bb) {
            float r  = sigf(ar[bb]);
            float u  = sigf(az[bb]);
            float n  = tanh_acc(fmaf(r, ah[bb], ai[bb]));
            float ho = hb2[bb * HD + j];
            hnew[bb] = (1.0f - u) * n + u * ho;
        }
        __syncthreads();
        #pragma unroll
        for (int bb = 0; bb < RPT; ++bb) hbuf[(2 * NB + g * RPT + bb) * HD + j] = hnew[bb];
        __syncthreads();

        // ================= logits + argmax ==================================
        // 512 threads: vv = tid&63 (vocab), rg = tid>>6 -> 2 rows each
        float acc2[2] = {0.f, 0.f};
        const float* h2b = hbuf + (2 * NB + rg * 2) * HD;
        #pragma unroll 4
        for (int k4 = 0; k4 < 64; ++k4) {
            float4 wv = g_owT[k4 * 64 + vv];
            const float* hk = h2b + k4 * 4;
            #pragma unroll
            for (int rr = 0; rr < 2; ++rr) {
                float4 hv = *reinterpret_cast<const float4*>(hk + rr * HD);
                acc2[rr] = fmaf(wv.w, hv.w, fmaf(wv.z, hv.z, fmaf(wv.y, hv.y, fmaf(wv.x, hv.x, acc2[rr]))));
            }
        }
        #pragma unroll
        for (int rr = 0; rr < 2; ++rr) {
            float lv  = acc2[rr] + ob;
            int   row = rg * 2 + rr;
            slog[row * TV + vv] = lv;
            out[((size_t)(b0 + row) * TSTEPS + t) * TV + vv] = lv;
        }
        __syncthreads();
        if (tid < NB) {
            const float* lr = slog + tid * TV;
            float best = lr[0];
            int   bi   = 0;
            #pragma unroll 8
            for (int v2 = 1; v2 < TV; ++v2) {
                float lvv = lr[v2];
                if (lvv > best) { best = lvv; bi = v2; }   // first-max semantics
            }
            stok[tid] = bi;
        }
        __syncthreads();
    }
}

// ---------------- launch ------------------------------------------------------
extern "C" void kernel_launch(void* const* d_in, const int* in_sizes, int n_in,
                              void* d_out, int out_size)
{
    const float* z     = (const float*)d_in[0];
    const float* emb   = (const float*)d_in[1];
    const float* z2h_w = (const float*)d_in[2];
    const float* z2h_b = (const float*)d_in[3];
    const float* out_w = (const float*)d_in[4];
    const float* out_b = (const float*)d_in[5];
    const float* w_ih0 = (const float*)d_in[6];
    const float* w_hh0 = (const float*)d_in[7];
    const float* b_ih0 = (const float*)d_in[8];
    const float* b_hh0 = (const float*)d_in[9];
    const float* w_ih1 = (const float*)d_in[10];
    const float* w_hh1 = (const float*)d_in[11];
    const float* b_ih1 = (const float*)d_in[12];
    const float* b_hh1 = (const float*)d_in[13];
    const float* w_ih2 = (const float*)d_in[14];
    const float* w_hh2 = (const float*)d_in[15];
    const float* b_ih2 = (const float*)d_in[16];
    const float* b_hh2 = (const float*)d_in[17];

    prep_kernel<<<768, 256>>>(w_hh0, w_hh1, w_hh2, w_ih1, w_ih2,
                              out_w, emb, w_ih0, b_ih0);

    const int smem = (3 * NB * HD + NB * TV) * (int)sizeof(float) + NB * (int)sizeof(int);
    cudaFuncSetAttribute(decoder_kernel, cudaFuncAttributeMaxDynamicSharedMemorySize, smem);

    decoder_kernel<<<4096 / NB, NTH, smem>>>(z, z2h_w, z2h_b,
                                             b_hh0, b_ih1, b_hh1, b_ih2, b_hh2,
                                             out_b, (float*)d_out);
}

// round 4
// speedup vs baseline: 1.3139x; 1.1690x over previous
#include <cuda_runtime.h>
#include <math.h>

// Model dims
#define NB      16      // batch rows per block
#define NP      8       // row pairs per block
#define NTH     512     // threads: 2 groups x 256 hidden units
#define GP      4       // pairs per group (NP/2)
#define HD      256     // hidden
#define TV      64      // vocab
#define TSTEPS  119     // T-1

typedef unsigned long long u64;

// ---------------- device-global scratch --------------------------------------
__device__ float4 g_whT[3][64 * 768];   // w_hh layers 0..2, [k4][768] float4
__device__ float4 g_wiT[2][64 * 768];   // w_ih layers 1..2
__device__ float4 g_owT[64 * 64];       // out_w [k4][64] float4
__device__ float  g_table[64 * 768];    // emb @ w_ih0^T + b_ih0

// ---------------- packed f32x2 helpers ---------------------------------------
__device__ __forceinline__ u64 rep2(float w) {
    u64 r; asm("mov.b64 %0, {%1, %1};" : "=l"(r) : "f"(w)); return r;
}
__device__ __forceinline__ u64 pack2(float lo, float hi) {
    u64 r; asm("mov.b64 %0, {%1, %2};" : "=l"(r) : "f"(lo), "f"(hi)); return r;
}
__device__ __forceinline__ void unpack2(u64 v, float& lo, float& hi) {
    asm("mov.b64 {%0, %1}, %2;" : "=f"(lo), "=f"(hi) : "l"(v));
}
__device__ __forceinline__ void fma2(u64& a, u64 b, u64 c) {
    asm("fma.rn.f32x2 %0, %1, %2, %0;" : "+l"(a) : "l"(b), "l"(c));
}

// ---------------- accurate activations ---------------------------------------
__device__ __forceinline__ float sigf(float x) { return 1.0f / (1.0f + expf(-x)); }
__device__ __forceinline__ float tanh_acc(float x) {
    float ax = fabsf(x);
    float e  = expf(-2.0f * ax);
    float t  = (1.0f - e) / (1.0f + e);
    return (x >= 0.0f) ? t : -t;
}

// ---------------- prep --------------------------------------------------------
__global__ void prep_kernel(const float* __restrict__ w_hh0,
                            const float* __restrict__ w_hh1,
                            const float* __restrict__ w_hh2,
                            const float* __restrict__ w_ih1,
                            const float* __restrict__ w_ih2,
                            const float* __restrict__ out_w,
                            const float* __restrict__ emb,
                            const float* __restrict__ w_ih0,
                            const float* __restrict__ b_ih0)
{
    int idx    = blockIdx.x * blockDim.x + threadIdx.x;
    int stride = gridDim.x * blockDim.x;

    for (int e = idx; e < 768 * 256; e += stride) {
        int row = e >> 8;
        int k   = e & 255;
        int di  = (k >> 2) * 768 + row;
        int kk  = k & 3;
        ((float*)&g_whT[0][di])[kk] = w_hh0[e];
        ((float*)&g_whT[1][di])[kk] = w_hh1[e];
        ((float*)&g_whT[2][di])[kk] = w_hh2[e];
        ((float*)&g_wiT[0][di])[kk] = w_ih1[e];
        ((float*)&g_wiT[1][di])[kk] = w_ih2[e];
    }
    for (int e = idx; e < 64 * 256; e += stride) {
        int v = e >> 8;
        int k = e & 255;
        ((float*)&g_owT[(k >> 2) * 64 + v])[k & 3] = out_w[e];
    }
    for (int e = idx; e < 64 * 768; e += stride) {
        int v  = e / 768;
        int jj = e - v * 768;
        const float* er = emb   + v  * 64;
        const float* wr = w_ih0 + jj * 64;
        float acc = b_ih0[jj];
        #pragma unroll 8
        for (int t = 0; t < 64; ++t) acc = fmaf(er[t], wr[t], acc);
        g_table[e] = acc;
    }
}

// Packed triple-stream GEMM: a{0,1,2}[p] += w{r,z,n}.x for 4 row-pairs.
// xb: paired smem base for this group's 4 pairs, layout [pair][k][2].
__device__ __forceinline__ void gemm3p(const float4* __restrict__ w4,
                                       const float*  __restrict__ xb,
                                       int j, u64* a0, u64* a1, u64* a2)
{
    #pragma unroll 2
    for (int k4 = 0; k4 < 64; ++k4) {
        float4 wr = w4[k4 * 768 + j];
        float4 wz = w4[k4 * 768 + j + 256];
        float4 wn = w4[k4 * 768 + j + 512];
        u64 wr0 = rep2(wr.x), wr1 = rep2(wr.y), wr2 = rep2(wr.z), wr3 = rep2(wr.w);
        u64 wz0 = rep2(wz.x), wz1 = rep2(wz.y), wz2 = rep2(wz.z), wz3 = rep2(wz.w);
        u64 wn0 = rep2(wn.x), wn1 = rep2(wn.y), wn2 = rep2(wn.z), wn3 = rep2(wn.w);
        const float* xk = xb + k4 * 8;
        #pragma unroll
        for (int p = 0; p < GP; ++p) {
            ulonglong2 xa = *reinterpret_cast<const ulonglong2*>(xk + p * HD * 2);
            ulonglong2 xc = *reinterpret_cast<const ulonglong2*>(xk + p * HD * 2 + 4);
            fma2(a0[p], wr0, xa.x); fma2(a1[p], wz0, xa.x); fma2(a2[p], wn0, xa.x);
            fma2(a0[p], wr1, xa.y); fma2(a1[p], wz1, xa.y); fma2(a2[p], wn1, xa.y);
            fma2(a0[p], wr2, xc.x); fma2(a1[p], wz2, xc.x); fma2(a2[p], wn2, xc.x);
            fma2(a0[p], wr3, xc.y); fma2(a1[p], wz3, xc.y); fma2(a2[p], wn3, xc.y);
        }
    }
}

// ---------------- main persistent decoder ------------------------------------
__global__ void __launch_bounds__(NTH, 1)
decoder_kernel(const float* __restrict__ z,
               const float* __restrict__ z2h_w,
               const float* __restrict__ z2h_b,
               const float* __restrict__ b_hh0,
               const float* __restrict__ b_ih1, const float* __restrict__ b_hh1,
               const float* __restrict__ b_ih2, const float* __restrict__ b_hh2,
               const float* __restrict__ out_b,
               float* __restrict__ out)
{
    extern __shared__ float smem[];
    float* hbuf = smem;                           // [3][NP][HD][2] paired
    float* slog = smem + 3 * NP * HD * 2;         // [NB][TV]
    int*   stok = (int*)(slog + NB * TV);         // [NB]

    const int tid = threadIdx.x;
    const int b0  = blockIdx.x * NB;
    const int j   = tid & 255;                    // hidden unit
    const int g   = tid >> 8;                     // group 0/1 -> pairs g*4..g*4+3

    // ---- init h0 = tanh(z @ z2h_w^T + z2h_b) into paired layout; tokens = 1
    for (int idx = tid; idx < NB * 768; idx += NTH) {
        int b = idx / 768;
        int u = idx - b * 768;                    // u = l*256 + jj
        const float* wr = z2h_w + u * 128;
        const float* zr = z + (size_t)(b0 + b) * 128;
        float acc = z2h_b[u];
        #pragma unroll 8
        for (int k = 0; k < 128; ++k) acc = fmaf(wr[k], zr[k], acc);
        int l  = u >> 8;
        int jj = u & 255;
        hbuf[((l * NP + (b >> 1)) * HD + jj) * 2 + (b & 1)] = tanh_acc(acc);
    }
    if (tid < NB) stok[tid] = 1;
    __syncthreads();

    // ---- hoisted per-thread constants
    const float c0r = b_hh0[j], c0z = b_hh0[j + 256], c0n = b_hh0[j + 512];
    const float c1r = b_ih1[j] + b_hh1[j];
    const float c1z = b_ih1[j + 256] + b_hh1[j + 256];
    const float c1i = b_ih1[j + 512];
    const float c1h = b_hh1[j + 512];
    const float c2r = b_ih2[j] + b_hh2[j];
    const float c2z = b_ih2[j + 256] + b_hh2[j + 256];
    const float c2i = b_ih2[j + 512];
    const float c2h = b_hh2[j + 512];
    const int   vv  = tid & 63;
    const int   rg  = tid >> 6;                   // 0..7 -> pair index for logits
    const float ob  = out_b[vv];

    // group-local paired bases
    float* hp0 = hbuf + (0 * NP + g * GP) * HD * 2;
    float* hp1 = hbuf + (1 * NP + g * GP) * HD * 2;
    float* hp2 = hbuf + (2 * NP + g * GP) * HD * 2;

    u64 ar[GP], az[GP], ai[GP], ah[GP], hnp[GP];

    for (int t = 0; t < TSTEPS; ++t) {
        // ================= layer 0 ==========================================
        #pragma unroll
        for (int p = 0; p < GP; ++p) {
            const float* t0 = g_table + stok[(g * GP + p) * 2 + 0] * 768;
            const float* t1 = g_table + stok[(g * GP + p) * 2 + 1] * 768;
            ar[p] = pack2(t0[j] + c0r,       t1[j] + c0r);
            az[p] = pack2(t0[j + 256] + c0z, t1[j + 256] + c0z);
            ai[p] = pack2(t0[j + 512],       t1[j + 512]);
            ah[p] = rep2(c0n);
        }
        gemm3p(g_whT[0], hp0, j, ar, az, ah);
        #pragma unroll
        for (int p = 0; p < GP; ++p) {
            float r0, r1, u0, u1, i0, i1, n0, n1, ho0, ho1;
            unpack2(ar[p], r0, r1); unpack2(az[p], u0, u1);
            unpack2(ai[p], i0, i1); unpack2(ah[p], n0, n1);
            unpack2(*(const u64*)(hp0 + p * HD * 2 + j * 2), ho0, ho1);
            float rr0 = sigf(r0), rr1 = sigf(r1);
            float uu0 = sigf(u0), uu1 = sigf(u1);
            float nn0 = tanh_acc(fmaf(rr0, n0, i0));
            float nn1 = tanh_acc(fmaf(rr1, n1, i1));
            hnp[p] = pack2((1.0f - uu0) * nn0 + uu0 * ho0,
                           (1.0f - uu1) * nn1 + uu1 * ho1);
        }
        __syncthreads();
        #pragma unroll
        for (int p = 0; p < GP; ++p)
            *(u64*)(hp0 + p * HD * 2 + j * 2) = hnp[p];
        __syncthreads();

        // ================= layer 1 ==========================================
        #pragma unroll
        for (int p = 0; p < GP; ++p) {
            ar[p] = rep2(c1r); az[p] = rep2(c1z); ai[p] = rep2(c1i); ah[p] = rep2(c1h);
        }
        gemm3p(g_wiT[0], hp0, j, ar, az, ai);
        gemm3p(g_whT[1], hp1, j, ar, az, ah);
        #pragma unroll
        for (int p = 0; p < GP; ++p) {
            float r0, r1, u0, u1, i0, i1, n0, n1, ho0, ho1;
            unpack2(ar[p], r0, r1); unpack2(az[p], u0, u1);
            unpack2(ai[p], i0, i1); unpack2(ah[p], n0, n1);
            unpack2(*(const u64*)(hp1 + p * HD * 2 + j * 2), ho0, ho1);
            float rr0 = sigf(r0), rr1 = sigf(r1);
            float uu0 = sigf(u0), uu1 = sigf(u1);
            float nn0 = tanh_acc(fmaf(rr0, n0, i0));
            float nn1 = tanh_acc(fmaf(rr1, n1, i1));
            hnp[p] = pack2((1.0f - uu0) * nn0 + uu0 * ho0,
                           (1.0f - uu1) * nn1 + uu1 * ho1);
        }
        __syncthreads();
        #pragma unroll
        for (int p = 0; p < GP; ++p)
            *(u64*)(hp1 + p * HD * 2 + j * 2) = hnp[p];
        __syncthreads();

        // ================= layer 2 ==========================================
        #pragma unroll
        for (int p = 0; p < GP; ++p) {
            ar[p] = rep2(c2r); az[p] = rep2(c2z); ai[p] = rep2(c2i); ah[p] = rep2(c2h);
        }
        gemm3p(g_wiT[1], hp1, j, ar, az, ai);
        gemm3p(g_whT[2], hp2, j, ar, az, ah);
        #pragma unroll
        for (int p = 0; p < GP; ++p) {
            float r0, r1, u0, u1, i0, i1, n0, n1, ho0, ho1;
            unpack2(ar[p], r0, r1); unpack2(az[p], u0, u1);
            unpack2(ai[p], i0, i1); unpack2(ah[p], n0, n1);
            unpack2(*(const u64*)(hp2 + p * HD * 2 + j * 2), ho0, ho1);
            float rr0 = sigf(r0), rr1 = sigf(r1);
            float uu0 = sigf(u0), uu1 = sigf(u1);
            float nn0 = tanh_acc(fmaf(rr0, n0, i0));
            float nn1 = tanh_acc(fmaf(rr1, n1, i1));
            hnp[p] = pack2((1.0f - uu0) * nn0 + uu0 * ho0,
                           (1.0f - uu1) * nn1 + uu1 * ho1);
        }
        __syncthreads();
        #pragma unroll
        for (int p = 0; p < GP; ++p)
            *(u64*)(hp2 + p * HD * 2 + j * 2) = hnp[p];
        __syncthreads();

        // ================= logits + argmax (packed pair per thread) =========
        u64 acc = 0ULL;                            // two fp32 zeros
        const float* hk = hbuf + (2 * NP + rg) * HD * 2;
        #pragma unroll 4
        for (int k4 = 0; k4 < 64; ++k4) {
            float4 wv = g_owT[k4 * 64 + vv];
            ulonglong2 xa = *reinterpret_cast<const ulonglong2*>(hk + k4 * 8);
            ulonglong2 xc = *reinterpret_cast<const ulonglong2*>(hk + k4 * 8 + 4);
            fma2(acc, rep2(wv.x), xa.x);
            fma2(acc, rep2(wv.y), xa.y);
            fma2(acc, rep2(wv.z), xc.x);
            fma2(acc, rep2(wv.w), xc.y);
        }
        float l0, l1;
        unpack2(acc, l0, l1);
        l0 += ob; l1 += ob;
        {
            int row0 = rg * 2, row1 = rg * 2 + 1;
            slog[row0 * TV + vv] = l0;
            slog[row1 * TV + vv] = l1;
            out[((size_t)(b0 + row0) * TSTEPS + t) * TV + vv] = l0;
            out[((size_t)(b0 + row1) * TSTEPS + t) * TV + vv] = l1;
        }
        __syncthreads();
        if (tid < NB) {
            const float* lr = slog + tid * TV;
            float best = lr[0];
            int   bi   = 0;
            #pragma unroll 8
            for (int v2 = 1; v2 < TV; ++v2) {
                float lvv = lr[v2];
                if (lvv > best) { best = lvv; bi = v2; }   // first-max semantics
            }
            stok[tid] = bi;
        }
        __syncthreads();
    }
}

// ---------------- launch ------------------------------------------------------
extern "C" void kernel_launch(void* const* d_in, const int* in_sizes, int n_in,
                              void* d_out, int out_size)
{
    const float* z     = (const float*)d_in[0];
    const float* emb   = (const float*)d_in[1];
    const float* z2h_w = (const float*)d_in[2];
    const float* z2h_b = (const float*)d_in[3];
    const float* out_w = (const float*)d_in[4];
    const float* out_b = (const float*)d_in[5];
    const float* w_ih0 = (const float*)d_in[6];
    const float* w_hh0 = (const float*)d_in[7];
    const float* b_ih0 = (const float*)d_in[8];
    const float* b_hh0 = (const float*)d_in[9];
    const float* w_ih1 = (const float*)d_in[10];
    const float* w_hh1 = (const float*)d_in[11];
    const float* b_ih1 = (const float*)d_in[12];
    const float* b_hh1 = (const float*)d_in[13];
    const float* w_ih2 = (const float*)d_in[14];
    const float* w_hh2 = (const float*)d_in[15];
    const float* b_ih2 = (const float*)d_in[16];
    const float* b_hh2 = (const float*)d_in[17];

    prep_kernel<<<768, 256>>>(w_hh0, w_hh1, w_hh2, w_ih1, w_ih2,
                              out_w, emb, w_ih0, b_ih0);

    const int smem = (3 * NP * HD * 2 + NB * TV) * (int)sizeof(float) + NB * (int)sizeof(int);
    cudaFuncSetAttribute(decoder_kernel, cudaFuncAttributeMaxDynamicSharedMemorySize, smem);

    decoder_kernel<<<4096 / NB, NTH, smem>>>(z, z2h_w, z2h_b,
                                             b_hh0, b_ih1, b_hh1, b_ih2, b_hh2,
                                             out_b, (float*)d_out);
}